// round 1
// baseline (speedup 1.0000x reference)
#include <cuda_runtime.h>
#include <math.h>
#include <stdint.h>

#define B   8
#define H   16
#define HD  128
#define D   2048
#define NB  512
#define BS  64
#define MB  64
#define KV  (MB*BS)      // 4096
#define NCHUNK 8
#define CHUNK  (KV/NCHUNK)  // 512

// ---------------- scratch (no allocations allowed) ----------------
__device__ float g_q[B*D];
__device__ float g_k[B*D];
__device__ float g_v[B*D];
__device__ float g_o[B*D];
__device__ float g_pm[B*H*NCHUNK];
__device__ float g_pl[B*H*NCHUNK];
__device__ float g_po[B*H*NCHUNK*HD];

__device__ __forceinline__ float warp_sum(float v) {
#pragma unroll
    for (int o = 16; o; o >>= 1) v += __shfl_xor_sync(0xffffffffu, v, o);
    return v;
}

// ---------------- GEMV: out[b, col] = X[b,:] . W[col,:] + bias[col] ----------------
// One block per output column; W row streamed once (coalesced float4),
// all 8 X rows served from L2 (64 KB working set).
__global__ void __launch_bounds__(256) proj_kernel(
    const float* __restrict__ X,     // [B, D]
    const float* __restrict__ W,     // [D, D] row-major
    const float* __restrict__ bias,  // [D]
    float* __restrict__ out)         // [B, D]
{
    int col = blockIdx.x;
    const float4* wrow = (const float4*)(W + (size_t)col * D);
    float acc[B];
#pragma unroll
    for (int b = 0; b < B; b++) acc[b] = 0.f;

    for (int i = threadIdx.x; i < D/4; i += 256) {
        float4 w4 = wrow[i];
#pragma unroll
        for (int b = 0; b < B; b++) {
            float4 x4 = ((const float4*)(X + (size_t)b * D))[i];
            acc[b] += w4.x*x4.x + w4.y*x4.y + w4.z*x4.z + w4.w*x4.w;
        }
    }

    __shared__ float red[8][B];
    int lane = threadIdx.x & 31, wid = threadIdx.x >> 5;
#pragma unroll
    for (int b = 0; b < B; b++) {
        float s = warp_sum(acc[b]);
        if (lane == 0) red[wid][b] = s;
    }
    __syncthreads();
    if (threadIdx.x < B) {
        float s = 0.f;
#pragma unroll
        for (int w = 0; w < 8; w++) s += red[w][threadIdx.x];
        out[(size_t)threadIdx.x * D + col] = s + bias[col];
    }
}

// ---------------- RoPE on q and k (in-place, double-precision angles) ----------------
__global__ void rope_qk(const int* __restrict__ hist) {
    int bh = blockIdx.x;        // b*H + h
    int b  = bh >> 4;
    int d  = threadIdx.x;       // 0..63
    int pos = hist[b];
    double inv = exp(-((double)(2*d) / 128.0) * log(10000.0));
    double f   = (double)pos * inv;
    float cf = (float)cos(f);
    float sf = (float)sin(f);
    int base = bh * HD;
    {
        float x1 = g_q[base + d], x2 = g_q[base + d + 64];
        g_q[base + d]      = x1*cf - x2*sf;
        g_q[base + d + 64] = x2*cf + x1*sf;
    }
    {
        float x1 = g_k[base + d], x2 = g_k[base + d + 64];
        g_k[base + d]      = x1*cf - x2*sf;
        g_k[base + d + 64] = x2*cf + x1*sf;
    }
}

// ---------------- split-KV attention partial ----------------
// grid (NCHUNK, H, B), 128 threads = 4 warps. Warp handles 4 consecutive keys
// per iteration (8 independent LDG.128 in flight), online softmax per warp,
// warps merged through smem; unnormalized (m, l, o) written per chunk.
__global__ void __launch_bounds__(128) attn_partial(
    const float* __restrict__ kc, const float* __restrict__ vc,
    const int* __restrict__ hist, const int* __restrict__ bofs)
{
    int c = blockIdx.x, h = blockIdx.y, b = blockIdx.z;
    int pos = hist[b];
    int L = pos + 1;                 // keys 0..pos inclusive (s==pos is the new token)
    int s0 = c * CHUNK;
    int idx = (b*H + h)*NCHUNK + c;
    int tid = threadIdx.x, lane = tid & 31, w = tid >> 5;

    if (s0 >= L) {
        if (tid == 0) { g_pm[idx] = -1e30f; g_pl[idx] = 0.f; }
        return;
    }
    int s1 = min(s0 + CHUNK, L);

    float4 q4 = *(const float4*)(g_q + (size_t)b*D + h*HD + lane*4);
    const float scale = 0.08838834764831845f;  // 1/sqrt(128)
    const float* knew = g_k + (size_t)b*D + h*HD;
    const float* vnew = g_v + (size_t)b*D + h*HD;

    float m = -1e30f, l = 0.f;
    float4 oa = make_float4(0.f, 0.f, 0.f, 0.f);

    for (int base = s0 + w*4; base < s1; base += 16) {
        float4 k4[4], v4[4];
        float  sc[4];
#pragma unroll
        for (int i = 0; i < 4; i++) {
            int s = base + i;
            if (s < s1) {
                const float *kr, *vr;
                if (s == pos) { kr = knew; vr = vnew; }
                else {
                    int blk = bofs[b*MB + (s >> 6)];
                    size_t off = (((size_t)blk*BS + (s & 63))*H + h)*(size_t)HD;
                    kr = kc + off; vr = vc + off;
                }
                k4[i] = *(const float4*)(kr + lane*4);
                v4[i] = *(const float4*)(vr + lane*4);
            } else {
                k4[i] = make_float4(0.f,0.f,0.f,0.f);
                v4[i] = make_float4(0.f,0.f,0.f,0.f);
            }
        }
#pragma unroll
        for (int i = 0; i < 4; i++) {
            float dv = q4.x*k4[i].x + q4.y*k4[i].y + q4.z*k4[i].z + q4.w*k4[i].w;
            sc[i] = warp_sum(dv) * scale;
            if (base + i >= s1) sc[i] = -1e30f;
        }
        float mx = fmaxf(fmaxf(sc[0], sc[1]), fmaxf(sc[2], sc[3]));
        float mn = fmaxf(m, mx);
        float corr = expf(m - mn);
        l *= corr;
        oa.x *= corr; oa.y *= corr; oa.z *= corr; oa.w *= corr;
#pragma unroll
        for (int i = 0; i < 4; i++) {
            float p = expf(sc[i] - mn);   // invalid lanes: exp(-1e30 - mn) == 0
            l += p;
            oa.x += p * v4[i].x;
            oa.y += p * v4[i].y;
            oa.z += p * v4[i].z;
            oa.w += p * v4[i].w;
        }
        m = mn;
    }

    // merge the 4 warps
    __shared__ float sm_m[4], sm_l[4];
    __shared__ float sm_o[4][HD];
    if (lane == 0) { sm_m[w] = m; sm_l[w] = l; }
    *(float4*)&sm_o[w][lane*4] = oa;
    __syncthreads();

    float M = fmaxf(fmaxf(sm_m[0], sm_m[1]), fmaxf(sm_m[2], sm_m[3]));
    float f0 = (sm_l[0] > 0.f) ? expf(sm_m[0] - M) : 0.f;
    float f1 = (sm_l[1] > 0.f) ? expf(sm_m[1] - M) : 0.f;
    float f2 = (sm_l[2] > 0.f) ? expf(sm_m[2] - M) : 0.f;
    float f3 = (sm_l[3] > 0.f) ? expf(sm_m[3] - M) : 0.f;

    int d = tid;  // 0..127
    float acc = sm_o[0][d]*f0 + sm_o[1][d]*f1 + sm_o[2][d]*f2 + sm_o[3][d]*f3;
    g_po[(size_t)idx*HD + d] = acc;
    if (tid == 0) {
        g_pm[idx] = M;
        g_pl[idx] = sm_l[0]*f0 + sm_l[1]*f1 + sm_l[2]*f2 + sm_l[3]*f3;
    }
}

// ---------------- combine split-KV partials ----------------
__global__ void __launch_bounds__(HD) attn_combine() {
    int bh = blockIdx.x;    // b*H + h
    int d  = threadIdx.x;   // 0..127
    float M = -1e30f;
#pragma unroll
    for (int c = 0; c < NCHUNK; c++) M = fmaxf(M, g_pm[bh*NCHUNK + c]);
    float Ls = 0.f, acc = 0.f;
#pragma unroll
    for (int c = 0; c < NCHUNK; c++) {
        float lc = g_pl[bh*NCHUNK + c];
        if (lc > 0.f) {
            float f = expf(g_pm[bh*NCHUNK + c] - M);
            Ls  += lc * f;
            acc += g_po[(size_t)(bh*NCHUNK + c)*HD + d] * f;
        }
    }
    g_o[(size_t)bh*HD + d] = acc / Ls;   // layout b*D + h*HD + d since D == H*HD
}

// ---------------- entry point ----------------
extern "C" void kernel_launch(void* const* d_in, const int* in_sizes, int n_in,
                              void* d_out, int out_size) {
    const float* hs   = (const float*)d_in[0];
    const float* kc   = (const float*)d_in[1];
    const float* vc   = (const float*)d_in[2];
    const float* Wq   = (const float*)d_in[3];
    const float* bq   = (const float*)d_in[4];
    const float* Wk   = (const float*)d_in[5];
    const float* bk   = (const float*)d_in[6];
    const float* Wv   = (const float*)d_in[7];
    const float* bv   = (const float*)d_in[8];
    const float* Wo   = (const float*)d_in[9];
    const float* bo   = (const float*)d_in[10];
    const int*   hist = (const int*)d_in[11];
    const int*   bofs = (const int*)d_in[12];
    float* out = (float*)d_out;

    float *gq, *gk, *gv, *go;
    cudaGetSymbolAddress((void**)&gq, g_q);
    cudaGetSymbolAddress((void**)&gk, g_k);
    cudaGetSymbolAddress((void**)&gv, g_v);
    cudaGetSymbolAddress((void**)&go, g_o);

    proj_kernel<<<D, 256>>>(hs, Wq, bq, gq);
    proj_kernel<<<D, 256>>>(hs, Wk, bk, gk);
    proj_kernel<<<D, 256>>>(hs, Wv, bv, gv);
    rope_qk<<<B*H, 64>>>(hist);
    attn_partial<<<dim3(NCHUNK, H, B), 128>>>(kc, vc, hist, bofs);
    attn_combine<<<B*H, HD>>>();
    proj_kernel<<<D, 256>>>(go, Wo, bo, out);
}

// round 2
// speedup vs baseline: 1.0562x; 1.0562x over previous
#include <cuda_runtime.h>
#include <math.h>
#include <stdint.h>

#define B   8
#define H   16
#define HD  128
#define D   2048
#define NB  512
#define BS  64
#define MB  64
#define KV  (MB*BS)      // 4096
#define NCHUNK 8
#define CHUNK  (KV/NCHUNK)  // 512

// ---------------- scratch (no allocations allowed) ----------------
__device__ float g_q[B*D];
__device__ float g_k[B*D];
__device__ float g_v[B*D];
__device__ float g_o[B*D];
__device__ float g_pm[B*H*NCHUNK];
__device__ float g_pl[B*H*NCHUNK];
__device__ float g_po[B*H*NCHUNK*HD];

__device__ __forceinline__ float warp_sum(float v) {
#pragma unroll
    for (int o = 16; o; o >>= 1) v += __shfl_xor_sync(0xffffffffu, v, o);
    return v;
}

// ---------------- tiled GEMV: 16 columns per block, X staged in smem ----------
// Block: 128 threads = 4 warps, each warp computes 4 columns concurrently.
// X [8 x 2048] processed in two 32KB smem passes. W rows streamed once (DRAM),
// X read from L2 only once per block (vs once per column before: 16x less L2).
template<int WHICH_SEL>
__device__ __forceinline__ void gemv16_body(
    const float* __restrict__ X, const float* __restrict__ W,
    const float* __restrict__ bias, float* __restrict__ out, int cblk)
{
    int tid = threadIdx.x, lane = tid & 31, w = tid >> 5;
    int c0 = cblk * 16 + w * 4;

    __shared__ float sX[B][1024];
    float acc[4][B];
#pragma unroll
    for (int j = 0; j < 4; j++)
#pragma unroll
        for (int b = 0; b < B; b++) acc[j][b] = 0.f;

#pragma unroll
    for (int p = 0; p < 2; p++) {
        __syncthreads();
        for (int i = tid; i < B * 256; i += 128) {
            int b = i >> 8, j = i & 255;
            ((float4*)sX[b])[j] = ((const float4*)(X + (size_t)b * D + p * 1024))[j];
        }
        __syncthreads();
#pragma unroll
        for (int kk = 0; kk < 1024; kk += 128) {
            int k = kk + lane * 4;
            float4 w4[4];
#pragma unroll
            for (int j = 0; j < 4; j++)
                w4[j] = *(const float4*)(W + (size_t)(c0 + j) * D + p * 1024 + k);
#pragma unroll
            for (int b = 0; b < B; b++) {
                float4 x4 = *(const float4*)(&sX[b][k]);
#pragma unroll
                for (int j = 0; j < 4; j++)
                    acc[j][b] += w4[j].x*x4.x + w4[j].y*x4.y + w4[j].z*x4.z + w4[j].w*x4.w;
            }
        }
    }

#pragma unroll
    for (int j = 0; j < 4; j++)
#pragma unroll
        for (int b = 0; b < B; b++) {
            float s = warp_sum(acc[j][b]);
            if (lane == j * 8 + b)
                out[(size_t)b * D + c0 + j] = s + bias[c0 + j];
        }
}

// Fused QKV: grid 3*128 blocks; blockIdx/128 selects the matrix.
__global__ void __launch_bounds__(128) qkv_kernel(
    const float* __restrict__ X,
    const float* __restrict__ Wq, const float* __restrict__ bq,
    const float* __restrict__ Wk, const float* __restrict__ bk,
    const float* __restrict__ Wv, const float* __restrict__ bv)
{
    int which = blockIdx.x >> 7;
    int cblk  = blockIdx.x & 127;
    const float* W    = (which == 0) ? Wq : (which == 1) ? Wk : Wv;
    const float* bias = (which == 0) ? bq : (which == 1) ? bk : bv;
    float* out        = (which == 0) ? g_q : (which == 1) ? g_k : g_v;
    gemv16_body<0>(X, W, bias, out, cblk);
}

// Output projection: grid 128 blocks.
__global__ void __launch_bounds__(128) oproj_kernel(
    const float* __restrict__ W, const float* __restrict__ bias,
    float* __restrict__ out)
{
    gemv16_body<1>(g_o, W, bias, out, blockIdx.x);
}

// ---------------- RoPE on q and k (fp32 fast path) ----------------
__global__ void rope_qk(const int* __restrict__ hist) {
    int bh = blockIdx.x;        // b*H + h
    int b  = bh >> 4;
    int d  = threadIdx.x;       // 0..63
    int pos = hist[b];
    // inv = 10000^(-d/64) = 2^(-d * log2(10000)/64)
    float inv = exp2f((float)d * -0.2076205059304601f);
    float f   = (float)pos * inv;
    float sf, cf;
    sincosf(f, &sf, &cf);
    int base = bh * HD;
    {
        float x1 = g_q[base + d], x2 = g_q[base + d + 64];
        g_q[base + d]      = x1*cf - x2*sf;
        g_q[base + d + 64] = x2*cf + x1*sf;
    }
    {
        float x1 = g_k[base + d], x2 = g_k[base + d + 64];
        g_k[base + d]      = x1*cf - x2*sf;
        g_k[base + d + 64] = x2*cf + x1*sf;
    }
}

// ---------------- split-KV attention partial ----------------
__global__ void __launch_bounds__(128) attn_partial(
    const float* __restrict__ kc, const float* __restrict__ vc,
    const int* __restrict__ hist, const int* __restrict__ bofs)
{
    int c = blockIdx.x, h = blockIdx.y, b = blockIdx.z;
    int pos = hist[b];
    int L = pos + 1;
    int s0 = c * CHUNK;
    int idx = (b*H + h)*NCHUNK + c;
    int tid = threadIdx.x, lane = tid & 31, w = tid >> 5;

    if (s0 >= L) {
        if (tid == 0) { g_pm[idx] = -1e30f; g_pl[idx] = 0.f; }
        return;
    }
    int s1 = min(s0 + CHUNK, L);

    __shared__ int sblk[MB];
    if (tid < MB) sblk[tid] = bofs[b*MB + tid];
    __syncthreads();

    float4 q4 = *(const float4*)(g_q + (size_t)b*D + h*HD + lane*4);
    const float scale = 0.08838834764831845f;  // 1/sqrt(128)
    const float* knew = g_k + (size_t)b*D + h*HD;
    const float* vnew = g_v + (size_t)b*D + h*HD;

    float m = -1e30f, l = 0.f;
    float4 oa = make_float4(0.f, 0.f, 0.f, 0.f);

    for (int base = s0 + w*4; base < s1; base += 16) {
        float4 k4[4], v4[4];
        float  sc[4];
#pragma unroll
        for (int i = 0; i < 4; i++) {
            int s = base + i;
            if (s < s1) {
                const float *kr, *vr;
                if (s == pos) { kr = knew; vr = vnew; }
                else {
                    int blk = sblk[s >> 6];
                    size_t off = (((size_t)blk*BS + (s & 63))*H + h)*(size_t)HD;
                    kr = kc + off; vr = vc + off;
                }
                k4[i] = *(const float4*)(kr + lane*4);
                v4[i] = *(const float4*)(vr + lane*4);
            } else {
                k4[i] = make_float4(0.f,0.f,0.f,0.f);
                v4[i] = make_float4(0.f,0.f,0.f,0.f);
            }
        }
#pragma unroll
        for (int i = 0; i < 4; i++) {
            float dv = q4.x*k4[i].x + q4.y*k4[i].y + q4.z*k4[i].z + q4.w*k4[i].w;
            sc[i] = warp_sum(dv) * scale;
            if (base + i >= s1) sc[i] = -1e30f;
        }
        float mx = fmaxf(fmaxf(sc[0], sc[1]), fmaxf(sc[2], sc[3]));
        float mn = fmaxf(m, mx);
        float corr = expf(m - mn);
        l *= corr;
        oa.x *= corr; oa.y *= corr; oa.z *= corr; oa.w *= corr;
#pragma unroll
        for (int i = 0; i < 4; i++) {
            float p = expf(sc[i] - mn);
            l += p;
            oa.x += p * v4[i].x;
            oa.y += p * v4[i].y;
            oa.z += p * v4[i].z;
            oa.w += p * v4[i].w;
        }
        m = mn;
    }

    __shared__ float sm_m[4], sm_l[4];
    __shared__ float sm_o[4][HD];
    if (lane == 0) { sm_m[w] = m; sm_l[w] = l; }
    *(float4*)&sm_o[w][lane*4] = oa;
    __syncthreads();

    float M = fmaxf(fmaxf(sm_m[0], sm_m[1]), fmaxf(sm_m[2], sm_m[3]));
    float f0 = (sm_l[0] > 0.f) ? expf(sm_m[0] - M) : 0.f;
    float f1 = (sm_l[1] > 0.f) ? expf(sm_m[1] - M) : 0.f;
    float f2 = (sm_l[2] > 0.f) ? expf(sm_m[2] - M) : 0.f;
    float f3 = (sm_l[3] > 0.f) ? expf(sm_m[3] - M) : 0.f;

    int d = tid;
    float acc = sm_o[0][d]*f0 + sm_o[1][d]*f1 + sm_o[2][d]*f2 + sm_o[3][d]*f3;
    g_po[(size_t)idx*HD + d] = acc;
    if (tid == 0) {
        g_pm[idx] = M;
        g_pl[idx] = sm_l[0]*f0 + sm_l[1]*f1 + sm_l[2]*f2 + sm_l[3]*f3;
    }
}

// ---------------- combine split-KV partials ----------------
__global__ void __launch_bounds__(HD) attn_combine() {
    int bh = blockIdx.x;
    int d  = threadIdx.x;
    float M = -1e30f;
#pragma unroll
    for (int c = 0; c < NCHUNK; c++) M = fmaxf(M, g_pm[bh*NCHUNK + c]);
    float Ls = 0.f, acc = 0.f;
#pragma unroll
    for (int c = 0; c < NCHUNK; c++) {
        float lc = g_pl[bh*NCHUNK + c];
        if (lc > 0.f) {
            float f = expf(g_pm[bh*NCHUNK + c] - M);
            Ls  += lc * f;
            acc += g_po[(size_t)(bh*NCHUNK + c)*HD + d] * f;
        }
    }
    g_o[(size_t)bh*HD + d] = acc / Ls;
}

// ---------------- entry point ----------------
extern "C" void kernel_launch(void* const* d_in, const int* in_sizes, int n_in,
                              void* d_out, int out_size) {
    const float* hs   = (const float*)d_in[0];
    const float* kc   = (const float*)d_in[1];
    const float* vc   = (const float*)d_in[2];
    const float* Wq   = (const float*)d_in[3];
    const float* bq   = (const float*)d_in[4];
    const float* Wk   = (const float*)d_in[5];
    const float* bk   = (const float*)d_in[6];
    const float* Wv   = (const float*)d_in[7];
    const float* bv   = (const float*)d_in[8];
    const float* Wo   = (const float*)d_in[9];
    const float* bo   = (const float*)d_in[10];
    const int*   hist = (const int*)d_in[11];
    const int*   bofs = (const int*)d_in[12];
    float* out = (float*)d_out;

    qkv_kernel<<<3*128, 128>>>(hs, Wq, bq, Wk, bk, Wv, bv);
    rope_qk<<<B*H, 64>>>(hist);
    attn_partial<<<dim3(NCHUNK, H, B), 128>>>(kc, vc, hist, bofs);
    attn_combine<<<B*H, HD>>>();
    oproj_kernel<<<128, 128>>>(Wo, bo, out);
}